// round 4
// baseline (speedup 1.0000x reference)
#include <cuda_runtime.h>

typedef unsigned long long u64;

#define B_   32
#define C_   3
#define T_   4096
#define V_   25
#define P_   1024
#define O_   128
#define K_   24      // 3 channels * 8 patch samples
#define F_   28
#define PT   16      // patches per block
#define NT   (4*PT + 4)   // 68 time samples per block
#define PPAD 20      // p-dim pad (80B stride: 16B-aligned LDS.128)
#define TPB  256

__device__ float2 g_Gd[K_ * O_];   // duplicated pairs, [k][o] = (g,g)

// ---------------------------------------------------------------------------
// Setup: build sM (28x8, 2-level symmetric DWT of an 8-sample patch) in
// parallel, fuse with W into duplicated pairs. 1 block, 256 threads, ~2us.
// ---------------------------------------------------------------------------
__global__ void build_G(const float* __restrict__ W) {
    __shared__ float sA1[7][8], sD1[7][8];
    __shared__ float sM[F_][8];
    const int tid = threadIdx.x;

    const float DEC_LO[8] = {
        -0.010597401784997278f,  0.032883011666982945f,
         0.030841381835986965f, -0.18703481171888114f,
        -0.02798376941698385f,   0.6308807679295904f,
         0.7148465705525415f,    0.23037781330885523f };
    const float DEC_HI[8] = {
        -0.23037781330885523f,   0.7148465705525415f,
        -0.6308807679295904f,   -0.02798376941698385f,
         0.18703481171888114f,   0.030841381835986965f,
        -0.032883011666982945f, -0.010597401784997278f };

    // Level 1: A1[i][k] = sum_j lo_rev[j] * [refl8(2i+j-6) == k]
    if (tid < 56) {
        int i = tid >> 3, k = tid & 7;
        float a = 0.f, d = 0.f;
        for (int j = 0; j < 8; j++) {
            int s = 2 * i + j - 6;
            if (s < 0)  s = -1 - s;
            if (s >= 8) s = 15 - s;
            if (s == k) { a += DEC_LO[7 - j]; d += DEC_HI[7 - j]; }
        }
        sA1[i][k] = a; sD1[i][k] = d;
    }
    __syncthreads();

    // Level 2 applied to A1/D1 rows: aa[i][k] = sum_j lo_rev[j]*A1[refl7(2i+j-6)][k]
    if (tid < 56) {
        int i = tid >> 3, k = tid & 7;
        float aa = 0.f, ad = 0.f, da = 0.f, dd = 0.f;
        for (int j = 0; j < 8; j++) {
            int s = 2 * i + j - 6;
            if (s < 0)  s = -1 - s;
            if (s >= 7) s = 13 - s;
            float lo = DEC_LO[7 - j], hi = DEC_HI[7 - j];
            aa += lo * sA1[s][k];  ad += hi * sA1[s][k];
            da += lo * sD1[s][k];  dd += hi * sD1[s][k];
        }
        // Feature order in reference: [aa, ad, dd, da]
        sM[i][k]      = aa;
        sM[7 + i][k]  = ad;
        sM[14 + i][k] = dd;
        sM[21 + i][k] = da;
    }
    __syncthreads();

    if (tid < O_) {
        int o = tid;
        for (int c = 0; c < C_; c++)
            for (int k = 0; k < 8; k++) {
                float g = 0.f;
                for (int f = 0; f < F_; f++)
                    g += W[o * (C_ * F_) + c * F_ + f] * sM[f][k];
                g_Gd[(c * 8 + k) * O_ + o] = make_float2(g, g);
            }
    }
}

// ---------------------------------------------------------------------------
// Fused kernel.  Block = (16-patch tile, batch): 400 positions x 128 channels.
//
// Stage 1: coalesced global read of x[c, t0..t0+68, :] ; each value scattered
//          to its <=2 windowed slots xw[k=c*8+j][v][p].
// Stage 2: register-tiled GEMM. Thread tile = 8 pos (same v, f32x2 pairs)
//          x 8 ch. Per k: 2 LDS.128 (x, shared addrs), 8 LDS.64 (dup-G,
//          72B stride -> banks 18*chgrp mod 32 all distinct), 32 fma.rn.f32x2.
// ---------------------------------------------------------------------------
__global__ void __launch_bounds__(TPB, 2)
wavelet_fused(const float* __restrict__ x, float* __restrict__ out) {
    extern __shared__ __align__(16) char smem[];
    float (*xw)[V_][PPAD] = reinterpret_cast<float (*)[V_][PPAD]>(smem);     // 48000 B
    u64   (*gd)[16][9]    = reinterpret_cast<u64   (*)[16][9]>(smem + 48000); // 27648 B

    const int b   = blockIdx.y;
    const int pt0 = blockIdx.x * PT;
    const int t0  = 4 * pt0;
    const int tid = threadIdx.x;

    // --- stage dup-G into padded smem ---
    for (int idx = tid; idx < K_ * O_; idx += TPB) {
        int k = idx >> 7;
        int o = idx & (O_ - 1);
        const float2 d = g_Gd[idx];
        gd[k][o >> 3][o & 7] = *reinterpret_cast<const u64*>(&d);
    }

    // --- stage x: coalesced read, windowed scatter (<=2 STS per value) ---
    const float* xb = x + (size_t)b * C_ * T_ * V_;
    for (int idx = tid; idx < C_ * NT * V_; idx += TPB) {
        int c  = idx / (NT * V_);
        int r  = idx - c * (NT * V_);
        int tl = r / V_;
        int v  = r - tl * V_;
        int t  = t0 + tl;
        if (t > T_ - 1) t = T_ - 1;          // edge padding
        float val = xb[(c * T_ + t) * V_ + v];
        int p = tl >> 2, j = tl & 3;
        if (p < PT)   xw[c * 8 + j][v][p]         = val;
        if (p >= 1)   xw[c * 8 + j + 4][v][p - 1] = val;
    }
    __syncthreads();

    // --- GEMM: 50 pos-groups x 16 ch-groups = 800 thread tiles, ragged loop ---
    for (int tile = tid; tile < 800; tile += TPB) {
        const int chgrp  = tile & 15;
        const int posgrp = tile >> 4;
        const int v      = posgrp >> 1;
        const int pl0    = (posgrp & 1) << 3;

        u64 acc[4][8];
#pragma unroll
        for (int pp = 0; pp < 4; pp++)
#pragma unroll
            for (int c = 0; c < 8; c++) acc[pp][c] = 0ULL;

#pragma unroll
        for (int k = 0; k < K_; k++) {
            const ulonglong2* xp = reinterpret_cast<const ulonglong2*>(&xw[k][v][pl0]);
            ulonglong2 xa = xp[0], xc = xp[1];          // 4 f32x2 position pairs
            u64 xv[4] = { xa.x, xa.y, xc.x, xc.y };

            const u64* gk = &gd[k][chgrp][0];
            u64 gv[8];
#pragma unroll
            for (int c = 0; c < 8; c++) gv[c] = gk[c];  // LDS.64, conflict-free

#pragma unroll
            for (int pp = 0; pp < 4; pp++)
#pragma unroll
                for (int c = 0; c < 8; c++)
                    asm("fma.rn.f32x2 %0, %1, %2, %0;"
                        : "+l"(acc[pp][c]) : "l"(gv[c]), "l"(xv[pp]));
        }

        float* orow = out + (((size_t)(b * V_ + v) * P_ + pt0 + pl0) << 7) + (chgrp << 3);
#pragma unroll
        for (int pp = 0; pp < 4; pp++) {
            float lo[8], hi[8];
#pragma unroll
            for (int c = 0; c < 8; c++)
                asm("mov.b64 {%0, %1}, %2;" : "=f"(lo[c]), "=f"(hi[c]) : "l"(acc[pp][c]));
            float* r0 = orow + (size_t)(2 * pp) * O_;
            *reinterpret_cast<float4*>(r0)          = make_float4(lo[0], lo[1], lo[2], lo[3]);
            *reinterpret_cast<float4*>(r0 + 4)      = make_float4(lo[4], lo[5], lo[6], lo[7]);
            *reinterpret_cast<float4*>(r0 + O_)     = make_float4(hi[0], hi[1], hi[2], hi[3]);
            *reinterpret_cast<float4*>(r0 + O_ + 4) = make_float4(hi[4], hi[5], hi[6], hi[7]);
        }
    }
}

// ---------------------------------------------------------------------------
extern "C" void kernel_launch(void* const* d_in, const int* in_sizes, int n_in,
                              void* d_out, int out_size) {
    const float* x = (const float*)d_in[0];
    const float* W = (const float*)d_in[1];
    if (n_in >= 2 && in_sizes[0] < in_sizes[1]) {
        const float* t = x; x = W; W = t;
    }

    const int smem_bytes = 48000 + 27648;   // 75648
    static int attr_set = 0;
    if (!attr_set) {
        cudaFuncSetAttribute(wavelet_fused,
                             cudaFuncAttributeMaxDynamicSharedMemorySize, smem_bytes);
        attr_set = 1;
    }

    build_G<<<1, 256>>>(W);

    dim3 grid(P_ / PT, B_);
    wavelet_fused<<<grid, TPB, smem_bytes>>>(x, (float*)d_out);
}

// round 5
// speedup vs baseline: 1.8619x; 1.8619x over previous
#include <cuda_runtime.h>

typedef unsigned long long u64;

#define B_   32
#define C_   3
#define T_   4096
#define V_   25
#define P_   1024
#define O_   128
#define K_   24      // 3 channels * 8 patch samples
#define F_   28
#define PT   16      // patches per block
#define NT   (4*PT + 4)   // 68 time samples per block
#define PPAD 20      // p-dim pad (80B row stride, 16B aligned)
#define TPB  256

#define XW_BYTES (K_ * V_ * PPAD * 4)        // 48000
#define GD_BYTES (K_ * 32 * 5 * 8)           // 30720
#define SMEM_BYTES (XW_BYTES + GD_BYTES)     // 78720

__device__ float2 g_Gd[K_ * O_];   // duplicated pairs, [k][o] = (g,g)

// ---------------------------------------------------------------------------
// Setup: build sM (28x8, 2-level symmetric DWT of an 8-sample patch) in
// parallel, fuse with W into duplicated pairs. 1 block, 256 threads.
// ---------------------------------------------------------------------------
__global__ void build_G(const float* __restrict__ W) {
    __shared__ float sA1[7][8], sD1[7][8];
    __shared__ float sM[F_][8];
    const int tid = threadIdx.x;

    const float DEC_LO[8] = {
        -0.010597401784997278f,  0.032883011666982945f,
         0.030841381835986965f, -0.18703481171888114f,
        -0.02798376941698385f,   0.6308807679295904f,
         0.7148465705525415f,    0.23037781330885523f };
    const float DEC_HI[8] = {
        -0.23037781330885523f,   0.7148465705525415f,
        -0.6308807679295904f,   -0.02798376941698385f,
         0.18703481171888114f,   0.030841381835986965f,
        -0.032883011666982945f, -0.010597401784997278f };

    if (tid < 56) {
        int i = tid >> 3, k = tid & 7;
        float a = 0.f, d = 0.f;
        for (int j = 0; j < 8; j++) {
            int s = 2 * i + j - 6;
            if (s < 0)  s = -1 - s;
            if (s >= 8) s = 15 - s;
            if (s == k) { a += DEC_LO[7 - j]; d += DEC_HI[7 - j]; }
        }
        sA1[i][k] = a; sD1[i][k] = d;
    }
    __syncthreads();

    if (tid < 56) {
        int i = tid >> 3, k = tid & 7;
        float aa = 0.f, ad = 0.f, da = 0.f, dd = 0.f;
        for (int j = 0; j < 8; j++) {
            int s = 2 * i + j - 6;
            if (s < 0)  s = -1 - s;
            if (s >= 7) s = 13 - s;
            float lo = DEC_LO[7 - j], hi = DEC_HI[7 - j];
            aa += lo * sA1[s][k];  ad += hi * sA1[s][k];
            da += lo * sD1[s][k];  dd += hi * sD1[s][k];
        }
        // Feature order in reference: [aa, ad, dd, da]
        sM[i][k]      = aa;
        sM[7 + i][k]  = ad;
        sM[14 + i][k] = dd;
        sM[21 + i][k] = da;
    }
    __syncthreads();

    if (tid < O_) {
        int o = tid;
        for (int c = 0; c < C_; c++)
            for (int k = 0; k < 8; k++) {
                float g = 0.f;
                for (int f = 0; f < F_; f++)
                    g += W[o * (C_ * F_) + c * F_ + f] * sM[f][k];
                g_Gd[(c * 8 + k) * O_ + o] = make_float2(g, g);
            }
    }
}

// ---------------------------------------------------------------------------
// Fused kernel.  Block = (16-patch tile, batch): 400 positions x 128 channels.
//
// Stage 1: coalesced global read of x tile; scatter into windowed layout
//          xw[k][v][p] (<=2 STS per value).
// Stage 2: register-tiled GEMM. Warp = 2 posgroups (half-warps) x 16 ch-groups
//          of 4 ch. Thread tile = 8 pos (4 f32x2 pairs) x 4 ch -> acc 32 regs.
//          Per k per warp: 2 LDS.128 (x) + 4 LDS.64 (G, bank-conflict-free:
//          40B group stride -> bank 10*lane mod 32 distinct per phase)
//          + 16 fma.rn.f32x2.
// ---------------------------------------------------------------------------
__global__ void __launch_bounds__(TPB, 2)
wavelet_fused(const float* __restrict__ x, float* __restrict__ out) {
    extern __shared__ __align__(16) char smem[];
    float (*xw)[V_][PPAD] = reinterpret_cast<float (*)[V_][PPAD]>(smem);
    u64   (*gd)[32][5]    = reinterpret_cast<u64   (*)[32][5]>(smem + XW_BYTES);

    const int b   = blockIdx.y;
    const int pt0 = blockIdx.x * PT;
    const int t0  = 4 * pt0;
    const int tid = threadIdx.x;

    // --- stage dup-G: gd[k][chgrp of 4 ch][4 pairs + 1 pad] ---
    for (int idx = tid; idx < K_ * O_; idx += TPB) {
        int k = idx >> 7;
        int o = idx & (O_ - 1);
        const float2 d = g_Gd[idx];
        gd[k][o >> 2][o & 3] = *reinterpret_cast<const u64*>(&d);
    }

    // --- stage x: coalesced read, windowed scatter ---
    const float* xb = x + (size_t)b * C_ * T_ * V_;
    for (int idx = tid; idx < C_ * NT * V_; idx += TPB) {
        int c  = idx / (NT * V_);
        int r  = idx - c * (NT * V_);
        int tl = r / V_;
        int v  = r - tl * V_;
        int t  = t0 + tl;
        if (t > T_ - 1) t = T_ - 1;          // edge padding
        float val = xb[(c * T_ + t) * V_ + v];
        int p = tl >> 2, j = tl & 3;
        if (p < PT)   xw[c * 8 + j][v][p]         = val;
        if (p >= 1)   xw[c * 8 + j + 4][v][p - 1] = val;
    }
    __syncthreads();

    // --- GEMM: 25 pos-pairs x 2 ch-halves = 50 warp-tiles over 8 warps ---
    const int warp = tid >> 5, lane = tid & 31;
    const int sub  = lane >> 4;         // which posgroup of the pair
    const int cg   = lane & 15;         // ch-group within half

    for (int wt = warp; wt < 50; wt += 8) {
        const int v     = wt >> 1;               // pos-pair index = v
        const int chalf = wt & 1;
        const int pl0   = sub * 8;
        const int chgrp = chalf * 16 + cg;       // 4-ch group, 0..31
        const int ch0   = chgrp * 4;

        u64 acc[4][4];
#pragma unroll
        for (int pp = 0; pp < 4; pp++)
#pragma unroll
            for (int c = 0; c < 4; c++) acc[pp][c] = 0ULL;

#pragma unroll
        for (int k = 0; k < K_; k++) {
            const float* xk = &xw[k][v][pl0];
            ulonglong2 xa = *reinterpret_cast<const ulonglong2*>(xk);      // pairs 0,1
            ulonglong2 xc = *reinterpret_cast<const ulonglong2*>(xk + 4);  // pairs 2,3
            u64 xv[4] = { xa.x, xa.y, xc.x, xc.y };

            const u64* gk = &gd[k][chgrp][0];
            u64 gv[4];
#pragma unroll
            for (int c = 0; c < 4; c++) gv[c] = gk[c];   // LDS.64, conflict-free

#pragma unroll
            for (int pp = 0; pp < 4; pp++)
#pragma unroll
                for (int c = 0; c < 4; c++)
                    asm("fma.rn.f32x2 %0, %1, %2, %0;"
                        : "+l"(acc[pp][c]) : "l"(gv[c]), "l"(xv[pp]));
        }

        float* obase = out + (((size_t)(b * V_ + v) * P_ + pt0 + pl0) << 7) + ch0;
#pragma unroll
        for (int pp = 0; pp < 4; pp++) {
            float lo[4], hi[4];
#pragma unroll
            for (int c = 0; c < 4; c++)
                asm("mov.b64 {%0, %1}, %2;" : "=f"(lo[c]), "=f"(hi[c]) : "l"(acc[pp][c]));
            float* r0 = obase + (size_t)(2 * pp) * O_;
            *reinterpret_cast<float4*>(r0)      = make_float4(lo[0], lo[1], lo[2], lo[3]);
            *reinterpret_cast<float4*>(r0 + O_) = make_float4(hi[0], hi[1], hi[2], hi[3]);
        }
    }
}

// ---------------------------------------------------------------------------
extern "C" void kernel_launch(void* const* d_in, const int* in_sizes, int n_in,
                              void* d_out, int out_size) {
    const float* x = (const float*)d_in[0];
    const float* W = (const float*)d_in[1];
    if (n_in >= 2 && in_sizes[0] < in_sizes[1]) {
        const float* t = x; x = W; W = t;
    }

    static int attr_set = 0;
    if (!attr_set) {
        cudaFuncSetAttribute(wavelet_fused,
                             cudaFuncAttributeMaxDynamicSharedMemorySize, SMEM_BYTES);
        attr_set = 1;
    }

    build_G<<<1, 256>>>(W);

    dim3 grid(P_ / PT, B_);
    wavelet_fused<<<grid, TPB, SMEM_BYTES>>>(x, (float*)d_out);
}

// round 7
// speedup vs baseline: 3.1616x; 1.6980x over previous
#include <cuda_runtime.h>

typedef unsigned long long u64;

#define B_   32
#define C_   3
#define T_   4096
#define V_   25
#define P_   1024
#define O_   128
#define K_   24      // 3 channels * 8 patch samples
#define F_   28
#define PT   16      // patches per block
#define NT   (4*PT + 4)   // 68 time samples per block
#define PPAD 20      // p-dim pad (80B row stride, 16B aligned)
#define TPB  256

#define XW_BYTES (K_ * V_ * PPAD * 4)        // 48000
#define GD_BYTES (K_ * 32 * 5 * 8)           // 30720
#define SMEM_BYTES (XW_BYTES + GD_BYTES)     // 78720

__device__ float2 g_Gd[K_ * O_];   // duplicated pairs, [k][o] = (g,g)

// ---------------------------------------------------------------------------
// Setup: build sM (28x8, 2-level symmetric DWT of an 8-sample patch) in
// parallel, fuse with W into duplicated pairs. 1 block, 256 threads.
// ---------------------------------------------------------------------------
__global__ void build_G(const float* __restrict__ W) {
    __shared__ float sA1[7][8], sD1[7][8];
    __shared__ float sM[F_][8];
    const int tid = threadIdx.x;

    const float DEC_LO[8] = {
        -0.010597401784997278f,  0.032883011666982945f,
         0.030841381835986965f, -0.18703481171888114f,
        -0.02798376941698385f,   0.6308807679295904f,
         0.7148465705525415f,    0.23037781330885523f };
    const float DEC_HI[8] = {
        -0.23037781330885523f,   0.7148465705525415f,
        -0.6308807679295904f,   -0.02798376941698385f,
         0.18703481171888114f,   0.030841381835986965f,
        -0.032883011666982945f, -0.010597401784997278f };

    if (tid < 56) {
        int i = tid >> 3, k = tid & 7;
        float a = 0.f, d = 0.f;
        for (int j = 0; j < 8; j++) {
            int s = 2 * i + j - 6;
            if (s < 0)  s = -1 - s;
            if (s >= 8) s = 15 - s;
            if (s == k) { a += DEC_LO[7 - j]; d += DEC_HI[7 - j]; }
        }
        sA1[i][k] = a; sD1[i][k] = d;
    }
    __syncthreads();

    if (tid < 56) {
        int i = tid >> 3, k = tid & 7;
        float aa = 0.f, ad = 0.f, da = 0.f, dd = 0.f;
        for (int j = 0; j < 8; j++) {
            int s = 2 * i + j - 6;
            if (s < 0)  s = -1 - s;
            if (s >= 7) s = 13 - s;
            float lo = DEC_LO[7 - j], hi = DEC_HI[7 - j];
            aa += lo * sA1[s][k];  ad += hi * sA1[s][k];
            da += lo * sD1[s][k];  dd += hi * sD1[s][k];
        }
        // Feature order in reference: [aa, ad, dd, da]
        sM[i][k]      = aa;
        sM[7 + i][k]  = ad;
        sM[14 + i][k] = dd;
        sM[21 + i][k] = da;
    }
    __syncthreads();

    if (tid < O_) {
        int o = tid;
        for (int c = 0; c < C_; c++)
            for (int k = 0; k < 8; k++) {
                float g = 0.f;
                for (int f = 0; f < F_; f++)
                    g += W[o * (C_ * F_) + c * F_ + f] * sM[f][k];
                g_Gd[(c * 8 + k) * O_ + o] = make_float2(g, g);
            }
    }
}

// ---------------------------------------------------------------------------
// Fused kernel.  Block = (16-patch tile, batch): 400 positions x 128 channels.
// Warp = 2 pos-subgroups x 16 ch-groups of 4 ch; thread tile 8 pos x 4 ch.
// k-loop unrolled by 4 ONLY (bounded live ranges -> no spills).
// ---------------------------------------------------------------------------
__global__ void __launch_bounds__(TPB, 2)
wavelet_fused(const float* __restrict__ x, float* __restrict__ out) {
    extern __shared__ __align__(16) char smem[];
    float (*xw)[V_][PPAD] = reinterpret_cast<float (*)[V_][PPAD]>(smem);
    u64   (*gd)[32][5]    = reinterpret_cast<u64   (*)[32][5]>(smem + XW_BYTES);

    const int b   = blockIdx.y;
    const int pt0 = blockIdx.x * PT;
    const int t0  = 4 * pt0;
    const int tid = threadIdx.x;

    // --- stage dup-G: gd[k][chgrp of 4 ch][4 pairs + 1 pad] ---
    for (int idx = tid; idx < K_ * O_; idx += TPB) {
        int k = idx >> 7;
        int o = idx & (O_ - 1);
        const float2 d = g_Gd[idx];
        gd[k][o >> 2][o & 3] = *reinterpret_cast<const u64*>(&d);
    }

    // --- stage x: coalesced read, windowed scatter ---
    const float* xb = x + (size_t)b * C_ * T_ * V_;
    for (int idx = tid; idx < C_ * NT * V_; idx += TPB) {
        int c  = idx / (NT * V_);
        int r  = idx - c * (NT * V_);
        int tl = r / V_;
        int v  = r - tl * V_;
        int t  = t0 + tl;
        if (t > T_ - 1) t = T_ - 1;          // edge padding
        float val = xb[(c * T_ + t) * V_ + v];
        int p = tl >> 2, j = tl & 3;
        if (p < PT)   xw[c * 8 + j][v][p]         = val;
        if (p >= 1)   xw[c * 8 + j + 4][v][p - 1] = val;
    }
    __syncthreads();

    // --- GEMM: 25 pos-pairs x 2 ch-halves = 50 warp-tiles over 8 warps ---
    const int warp = tid >> 5, lane = tid & 31;
    const int sub  = lane >> 4;         // which posgroup of the pair
    const int cg   = lane & 15;         // ch-group within half

#pragma unroll 1
    for (int wt = warp; wt < 50; wt += 8) {
        const int v     = wt >> 1;               // pos-pair index = v
        const int chalf = wt & 1;
        const int pl0   = sub * 8;
        const int chgrp = chalf * 16 + cg;       // 4-ch group, 0..31
        const int ch0   = chgrp * 4;

        u64 acc[4][4];
#pragma unroll
        for (int pp = 0; pp < 4; pp++)
#pragma unroll
            for (int c = 0; c < 4; c++) acc[pp][c] = 0ULL;

#pragma unroll 4
        for (int k = 0; k < K_; k++) {
            const float* xk = &xw[k][v][pl0];
            ulonglong2 xa = *reinterpret_cast<const ulonglong2*>(xk);      // pairs 0,1
            ulonglong2 xc = *reinterpret_cast<const ulonglong2*>(xk + 4);  // pairs 2,3
            u64 xv[4] = { xa.x, xa.y, xc.x, xc.y };

            const u64* gk = &gd[k][chgrp][0];
            u64 gv[4];
#pragma unroll
            for (int c = 0; c < 4; c++) gv[c] = gk[c];   // LDS.64, conflict-free

#pragma unroll
            for (int pp = 0; pp < 4; pp++)
#pragma unroll
                for (int c = 0; c < 4; c++)
                    asm("fma.rn.f32x2 %0, %1, %2, %0;"
                        : "+l"(acc[pp][c]) : "l"(gv[c]), "l"(xv[pp]));
        }

        float* obase = out + (((size_t)(b * V_ + v) * P_ + pt0 + pl0) << 7) + ch0;
#pragma unroll
        for (int pp = 0; pp < 4; pp++) {
            float lo[4], hi[4];
#pragma unroll
            for (int c = 0; c < 4; c++)
                asm("mov.b64 {%0, %1}, %2;" : "=f"(lo[c]), "=f"(hi[c]) : "l"(acc[pp][c]));
            float* r0 = obase + (size_t)(2 * pp) * O_;
            *reinterpret_cast<float4*>(r0)      = make_float4(lo[0], lo[1], lo[2], lo[3]);
            *reinterpret_cast<float4*>(r0 + O_) = make_float4(hi[0], hi[1], hi[2], hi[3]);
        }
    }
}

// ---------------------------------------------------------------------------
extern "C" void kernel_launch(void* const* d_in, const int* in_sizes, int n_in,
                              void* d_out, int out_size) {
    const float* x = (const float*)d_in[0];
    const float* W = (const float*)d_in[1];
    if (n_in >= 2 && in_sizes[0] < in_sizes[1]) {
        const float* t = x; x = W; W = t;
    }

    static int attr_set = 0;
    if (!attr_set) {
        cudaFuncSetAttribute(wavelet_fused,
                             cudaFuncAttributeMaxDynamicSharedMemorySize, SMEM_BYTES);
        attr_set = 1;
    }

    build_G<<<1, 256>>>(W);

    dim3 grid(P_ / PT, B_);
    wavelet_fused<<<grid, TPB, SMEM_BYTES>>>(x, (float*)d_out);
}

// round 9
// speedup vs baseline: 3.5427x; 1.1205x over previous
#include <cuda_runtime.h>

typedef unsigned long long u64;

#define B_   32
#define C_   3
#define T_   4096
#define V_   25
#define P_   1024
#define O_   128
#define K_   24      // 3 channels * 8 patch samples
#define F_   28
#define PT   16      // patches per block
#define NT   (4*PT + 4)   // 68 time samples per block
#define PPAD 18      // p-dim pad (72B row stride, 8B aligned)
#define TPB  256

#define XW_BYTES (K_ * V_ * PPAD * 4)        // 43200
#define GD_BYTES (K_ * 32 * 5 * 8)           // 30720
#define SMEM_BYTES (XW_BYTES + GD_BYTES)     // 73920  -> 3 CTAs/SM

__device__ float2 g_Gd[K_ * O_];   // duplicated pairs, [k][o] = (g,g)

// ---------------------------------------------------------------------------
// Setup: build sM (28x8, 2-level symmetric DWT of an 8-sample patch) in
// parallel, fuse with W into duplicated pairs. 1 block, 256 threads.
// ---------------------------------------------------------------------------
__global__ void build_G(const float* __restrict__ W) {
    __shared__ float sA1[7][8], sD1[7][8];
    __shared__ float sM[F_][8];
    const int tid = threadIdx.x;

    const float DEC_LO[8] = {
        -0.010597401784997278f,  0.032883011666982945f,
         0.030841381835986965f, -0.18703481171888114f,
        -0.02798376941698385f,   0.6308807679295904f,
         0.7148465705525415f,    0.23037781330885523f };
    const float DEC_HI[8] = {
        -0.23037781330885523f,   0.7148465705525415f,
        -0.6308807679295904f,   -0.02798376941698385f,
         0.18703481171888114f,   0.030841381835986965f,
        -0.032883011666982945f, -0.010597401784997278f };

    if (tid < 56) {
        int i = tid >> 3, k = tid & 7;
        float a = 0.f, d = 0.f;
        for (int j = 0; j < 8; j++) {
            int s = 2 * i + j - 6;
            if (s < 0)  s = -1 - s;
            if (s >= 8) s = 15 - s;
            if (s == k) { a += DEC_LO[7 - j]; d += DEC_HI[7 - j]; }
        }
        sA1[i][k] = a; sD1[i][k] = d;
    }
    __syncthreads();

    if (tid < 56) {
        int i = tid >> 3, k = tid & 7;
        float aa = 0.f, ad = 0.f, da = 0.f, dd = 0.f;
        for (int j = 0; j < 8; j++) {
            int s = 2 * i + j - 6;
            if (s < 0)  s = -1 - s;
            if (s >= 7) s = 13 - s;
            float lo = DEC_LO[7 - j], hi = DEC_HI[7 - j];
            aa += lo * sA1[s][k];  ad += hi * sA1[s][k];
            da += lo * sD1[s][k];  dd += hi * sD1[s][k];
        }
        // Feature order in reference: [aa, ad, dd, da]
        sM[i][k]      = aa;
        sM[7 + i][k]  = ad;
        sM[14 + i][k] = dd;
        sM[21 + i][k] = da;
    }
    __syncthreads();

    if (tid < O_) {
        int o = tid;
        for (int c = 0; c < C_; c++)
            for (int k = 0; k < 8; k++) {
                float g = 0.f;
                for (int f = 0; f < F_; f++)
                    g += W[o * (C_ * F_) + c * F_ + f] * sM[f][k];
                g_Gd[(c * 8 + k) * O_ + o] = make_float2(g, g);
            }
    }
}

// ---------------------------------------------------------------------------
// Fused kernel.  Block = (16-patch tile, batch): 400 positions x 128 channels.
// Warp = 2 pos-subgroups x 16 ch-groups of 4 ch; thread tile 8 pos x 4 ch.
// k-loop unrolled by 2; regs capped for 3 CTAs/SM.
// ---------------------------------------------------------------------------
__global__ void __launch_bounds__(TPB, 3)
wavelet_fused(const float* __restrict__ x, float* __restrict__ out) {
    extern __shared__ __align__(16) char smem[];
    float (*xw)[V_][PPAD] = reinterpret_cast<float (*)[V_][PPAD]>(smem);
    u64   (*gd)[32][5]    = reinterpret_cast<u64   (*)[32][5]>(smem + XW_BYTES);

    const int b   = blockIdx.y;
    const int pt0 = blockIdx.x * PT;
    const int t0  = 4 * pt0;
    const int tid = threadIdx.x;

    // --- stage dup-G: gd[k][chgrp of 4 ch][4 pairs + 1 pad] ---
    for (int idx = tid; idx < K_ * O_; idx += TPB) {
        int k = idx >> 7;
        int o = idx & (O_ - 1);
        const float2 d = g_Gd[idx];
        gd[k][o >> 2][o & 3] = *reinterpret_cast<const u64*>(&d);
    }

    // --- stage x: coalesced read, windowed scatter ---
    const float* xb = x + (size_t)b * C_ * T_ * V_;
    for (int idx = tid; idx < C_ * NT * V_; idx += TPB) {
        int c  = idx / (NT * V_);
        int r  = idx - c * (NT * V_);
        int tl = r / V_;
        int v  = r - tl * V_;
        int t  = t0 + tl;
        if (t > T_ - 1) t = T_ - 1;          // edge padding
        float val = xb[(c * T_ + t) * V_ + v];
        int p = tl >> 2, j = tl & 3;
        if (p < PT)   xw[c * 8 + j][v][p]         = val;
        if (p >= 1)   xw[c * 8 + j + 4][v][p - 1] = val;
    }
    __syncthreads();

    // --- GEMM: 25 pos-pairs x 2 ch-halves = 50 warp-tiles over 8 warps ---
    const int warp = tid >> 5, lane = tid & 31;
    const int sub  = lane >> 4;         // which posgroup of the pair
    const int cg   = lane & 15;         // ch-group within half

#pragma unroll 1
    for (int wt = warp; wt < 50; wt += 8) {
        const int v     = wt >> 1;               // pos-pair index = v
        const int chalf = wt & 1;
        const int pl0   = sub * 8;
        const int chgrp = chalf * 16 + cg;       // 4-ch group, 0..31
        const int ch0   = chgrp * 4;

        u64 acc[4][4];
#pragma unroll
        for (int pp = 0; pp < 4; pp++)
#pragma unroll
            for (int c = 0; c < 4; c++) acc[pp][c] = 0ULL;

#pragma unroll 2
        for (int k = 0; k < K_; k++) {
            const u64* xk = reinterpret_cast<const u64*>(&xw[k][v][pl0]);
            u64 xv[4];
#pragma unroll
            for (int i = 0; i < 4; i++) xv[i] = xk[i];   // LDS.64, 2-addr broadcast

            const u64* gk = &gd[k][chgrp][0];
            u64 gv[4];
#pragma unroll
            for (int c = 0; c < 4; c++) gv[c] = gk[c];   // LDS.64, conflict-free

#pragma unroll
            for (int pp = 0; pp < 4; pp++)
#pragma unroll
                for (int c = 0; c < 4; c++)
                    asm("fma.rn.f32x2 %0, %1, %2, %0;"
                        : "+l"(acc[pp][c]) : "l"(gv[c]), "l"(xv[pp]));
        }

        float* obase = out + (((size_t)(b * V_ + v) * P_ + pt0 + pl0) << 7) + ch0;
#pragma unroll
        for (int pp = 0; pp < 4; pp++) {
            float lo[4], hi[4];
#pragma unroll
            for (int c = 0; c < 4; c++)
                asm("mov.b64 {%0, %1}, %2;" : "=f"(lo[c]), "=f"(hi[c]) : "l"(acc[pp][c]));
            float* r0 = obase + (size_t)(2 * pp) * O_;
            *reinterpret_cast<float4*>(r0)      = make_float4(lo[0], lo[1], lo[2], lo[3]);
            *reinterpret_cast<float4*>(r0 + O_) = make_float4(hi[0], hi[1], hi[2], hi[3]);
        }
    }
}

// ---------------------------------------------------------------------------
extern "C" void kernel_launch(void* const* d_in, const int* in_sizes, int n_in,
                              void* d_out, int out_size) {
    const float* x = (const float*)d_in[0];
    const float* W = (const float*)d_in[1];
    if (n_in >= 2 && in_sizes[0] < in_sizes[1]) {
        const float* t = x; x = W; W = t;
    }

    static int attr_set = 0;
    if (!attr_set) {
        cudaFuncSetAttribute(wavelet_fused,
                             cudaFuncAttributeMaxDynamicSharedMemorySize, SMEM_BYTES);
        attr_set = 1;
    }

    build_G<<<1, 256>>>(W);

    dim3 grid(P_ / PT, B_);
    wavelet_fused<<<grid, TPB, SMEM_BYTES>>>(x, (float*)d_out);
}

// round 10
// speedup vs baseline: 3.5539x; 1.0032x over previous
#include <cuda_runtime.h>

typedef unsigned long long u64;

#define B_   32
#define C_   3
#define T_   4096
#define V_   25
#define P_   1024
#define O_   128
#define K_   24      // 3 channels * 8 patch samples
#define F_   28
#define PT   16      // patches per block
#define NT   (4*PT + 4)   // 68 time samples per block
#define PPAD 18      // p-dim pad (72B row stride, 8B aligned)
#define TPB  256

#define XW_BYTES (K_ * V_ * PPAD * 4)        // 43200
#define GD_BYTES (K_ * 32 * 5 * 8)           // 30720
#define SMEM_BYTES (XW_BYTES + GD_BYTES)     // 73920  -> 3 CTAs/SM

__device__ float2 g_Gd[K_ * O_];   // duplicated pairs, [k][o] = (g,g)

// ---------------------------------------------------------------------------
// Setup: build sM (28x8, 2-level symmetric DWT of an 8-sample patch) in
// parallel, fuse with W into duplicated pairs. 1 block, 256 threads.
// ---------------------------------------------------------------------------
__global__ void build_G(const float* __restrict__ W) {
    __shared__ float sA1[7][8], sD1[7][8];
    __shared__ float sM[F_][8];
    const int tid = threadIdx.x;

    const float DEC_LO[8] = {
        -0.010597401784997278f,  0.032883011666982945f,
         0.030841381835986965f, -0.18703481171888114f,
        -0.02798376941698385f,   0.6308807679295904f,
         0.7148465705525415f,    0.23037781330885523f };
    const float DEC_HI[8] = {
        -0.23037781330885523f,   0.7148465705525415f,
        -0.6308807679295904f,   -0.02798376941698385f,
         0.18703481171888114f,   0.030841381835986965f,
        -0.032883011666982945f, -0.010597401784997278f };

    if (tid < 56) {
        int i = tid >> 3, k = tid & 7;
        float a = 0.f, d = 0.f;
        for (int j = 0; j < 8; j++) {
            int s = 2 * i + j - 6;
            if (s < 0)  s = -1 - s;
            if (s >= 8) s = 15 - s;
            if (s == k) { a += DEC_LO[7 - j]; d += DEC_HI[7 - j]; }
        }
        sA1[i][k] = a; sD1[i][k] = d;
    }
    __syncthreads();

    if (tid < 56) {
        int i = tid >> 3, k = tid & 7;
        float aa = 0.f, ad = 0.f, da = 0.f, dd = 0.f;
        for (int j = 0; j < 8; j++) {
            int s = 2 * i + j - 6;
            if (s < 0)  s = -1 - s;
            if (s >= 7) s = 13 - s;
            float lo = DEC_LO[7 - j], hi = DEC_HI[7 - j];
            aa += lo * sA1[s][k];  ad += hi * sA1[s][k];
            da += lo * sD1[s][k];  dd += hi * sD1[s][k];
        }
        // Feature order in reference: [aa, ad, dd, da]
        sM[i][k]      = aa;
        sM[7 + i][k]  = ad;
        sM[14 + i][k] = dd;
        sM[21 + i][k] = da;
    }
    __syncthreads();

    if (tid < O_) {
        int o = tid;
        for (int c = 0; c < C_; c++)
            for (int k = 0; k < 8; k++) {
                float g = 0.f;
                for (int f = 0; f < F_; f++)
                    g += W[o * (C_ * F_) + c * F_ + f] * sM[f][k];
                g_Gd[(c * 8 + k) * O_ + o] = make_float2(g, g);
            }
    }
}

// ---------------------------------------------------------------------------
// Fused kernel.  Block = (16-patch tile, batch): 400 positions x 128 channels.
// Warp = 2 pos-subgroups x 16 ch-groups of 4 ch; thread tile 8 pos x 4 ch.
// k-loop unrolled by 2; regs capped for 3 CTAs/SM.
// ---------------------------------------------------------------------------
__global__ void __launch_bounds__(TPB, 3)
wavelet_fused(const float* __restrict__ x, float* __restrict__ out) {
    extern __shared__ __align__(16) char smem[];
    float (*xw)[V_][PPAD] = reinterpret_cast<float (*)[V_][PPAD]>(smem);
    u64   (*gd)[32][5]    = reinterpret_cast<u64   (*)[32][5]>(smem + XW_BYTES);

    const int b   = blockIdx.y;
    const int pt0 = blockIdx.x * PT;
    const int t0  = 4 * pt0;
    const int tid = threadIdx.x;

    // --- stage dup-G: gd[k][chgrp of 4 ch][4 pairs + 1 pad] ---
    for (int idx = tid; idx < K_ * O_; idx += TPB) {
        int k = idx >> 7;
        int o = idx & (O_ - 1);
        const float2 d = g_Gd[idx];
        gd[k][o >> 2][o & 3] = *reinterpret_cast<const u64*>(&d);
    }

    // --- stage x: coalesced read, windowed scatter ---
    const float* xb = x + (size_t)b * C_ * T_ * V_;
    for (int idx = tid; idx < C_ * NT * V_; idx += TPB) {
        int c  = idx / (NT * V_);
        int r  = idx - c * (NT * V_);
        int tl = r / V_;
        int v  = r - tl * V_;
        int t  = t0 + tl;
        if (t > T_ - 1) t = T_ - 1;          // edge padding
        float val = xb[(c * T_ + t) * V_ + v];
        int p = tl >> 2, j = tl & 3;
        if (p < PT)   xw[c * 8 + j][v][p]         = val;
        if (p >= 1)   xw[c * 8 + j + 4][v][p - 1] = val;
    }
    __syncthreads();

    // --- GEMM: 25 pos-pairs x 2 ch-halves = 50 warp-tiles over 8 warps ---
    const int warp = tid >> 5, lane = tid & 31;
    const int sub  = lane >> 4;         // which posgroup of the pair
    const int cg   = lane & 15;         // ch-group within half

#pragma unroll 1
    for (int wt = warp; wt < 50; wt += 8) {
        const int v     = wt >> 1;               // pos-pair index = v
        const int chalf = wt & 1;
        const int pl0   = sub * 8;
        const int chgrp = chalf * 16 + cg;       // 4-ch group, 0..31
        const int ch0   = chgrp * 4;

        u64 acc[4][4];
#pragma unroll
        for (int pp = 0; pp < 4; pp++)
#pragma unroll
            for (int c = 0; c < 4; c++) acc[pp][c] = 0ULL;

#pragma unroll 2
        for (int k = 0; k < K_; k++) {
            const u64* xk = reinterpret_cast<const u64*>(&xw[k][v][pl0]);
            u64 xv[4];
#pragma unroll
            for (int i = 0; i < 4; i++) xv[i] = xk[i];   // LDS.64, 2-addr broadcast

            const u64* gk = &gd[k][chgrp][0];
            u64 gv[4];
#pragma unroll
            for (int c = 0; c < 4; c++) gv[c] = gk[c];   // LDS.64, conflict-free

#pragma unroll
            for (int pp = 0; pp < 4; pp++)
#pragma unroll
                for (int c = 0; c < 4; c++)
                    asm("fma.rn.f32x2 %0, %1, %2, %0;"
                        : "+l"(acc[pp][c]) : "l"(gv[c]), "l"(xv[pp]));
        }

        float* obase = out + (((size_t)(b * V_ + v) * P_ + pt0 + pl0) << 7) + ch0;
#pragma unroll
        for (int pp = 0; pp < 4; pp++) {
            float lo[4], hi[4];
#pragma unroll
            for (int c = 0; c < 4; c++)
                asm("mov.b64 {%0, %1}, %2;" : "=f"(lo[c]), "=f"(hi[c]) : "l"(acc[pp][c]));
            float* r0 = obase + (size_t)(2 * pp) * O_;
            *reinterpret_cast<float4*>(r0)      = make_float4(lo[0], lo[1], lo[2], lo[3]);
            *reinterpret_cast<float4*>(r0 + O_) = make_float4(hi[0], hi[1], hi[2], hi[3]);
        }
    }
}

// ---------------------------------------------------------------------------
extern "C" void kernel_launch(void* const* d_in, const int* in_sizes, int n_in,
                              void* d_out, int out_size) {
    const float* x = (const float*)d_in[0];
    const float* W = (const float*)d_in[1];
    if (n_in >= 2 && in_sizes[0] < in_sizes[1]) {
        const float* t = x; x = W; W = t;
    }

    static int attr_set = 0;
    if (!attr_set) {
        cudaFuncSetAttribute(wavelet_fused,
                             cudaFuncAttributeMaxDynamicSharedMemorySize, SMEM_BYTES);
        attr_set = 1;
    }

    build_G<<<1, 256>>>(W);

    dim3 grid(P_ / PT, B_);
    wavelet_fused<<<grid, TPB, SMEM_BYTES>>>(x, (float*)d_out);
}